// round 4
// baseline (speedup 1.0000x reference)
#include <cuda_runtime.h>
#include <cuda_pipeline.h>
#include <cstdint>
#include <cstddef>

// ---------------- problem constants (fixed by dataset) ----------------
#define S_      4
#define DIM_    2048
#define NSEQ_   2048
#define B_      4
#define KTOT_   8192          // S*DIM
#define NTOK_   8192          // B*N
#define NW_     24            // 20 alpha cols + 4 beta cols
#define NACC_   25            // 24 dots + sumsq
#define TOK_    32            // tokens per reduce CTA
#define KC_     64            // k elements per chunk
#define PAIRS_  32            // k-pairs per chunk
#define NCHUNK_ 128           // KTOT_/KC_
#define XROW_   68            // padded smem row (floats): %4==0 for 16B cp.async, odd/32 for low conflicts

// ---------------- device scratch (no allocation allowed) ----------------
__device__ __align__(16) float2 g_wpack[(KTOT_ / 2) * NW_];  // 768 KB packed folded weights
__device__ __align__(16) float  g_dots[NTOK_ * 32];          // 25 sums per token, padded to 32
__device__ __align__(16) float  g_coef[NTOK_ * 16];          // per-token 4x4 mixing matrix

// Packed fp32x2 FMA (Blackwell FFMA2): 2 MACs per issue slot
__device__ __forceinline__ float2 ffma2(float2 a, float2 b, float2 c) {
    float2 d;
    asm("fma.rn.f32x2 %0, %1, %2, %3;"
        : "=l"(*reinterpret_cast<unsigned long long*>(&d))
        : "l"(*reinterpret_cast<const unsigned long long*>(&a)),
          "l"(*reinterpret_cast<const unsigned long long*>(&b)),
          "l"(*reinterpret_cast<const unsigned long long*>(&c)));
    return d;
}

// ---------------------------------------------------------------------------
// Kernel 0: fold gamma into the weights and interleave by k-parity:
//   g_wpack[p*24 + j] = ( (1+g[2p])*W[2p][j], (1+g[2p+1])*W[2p+1][j] )
// so FFMA2 accumulators hold (even-k, odd-k) partial sums.
// ---------------------------------------------------------------------------
__global__ void prep_kernel(const float* __restrict__ gamma,
                            const float* __restrict__ afn,   // (8192, 20)
                            const float* __restrict__ bfn)   // (8192, 4)
{
    int idx = blockIdx.x * blockDim.x + threadIdx.x;
    if (idx >= (KTOT_ / 2) * NW_) return;
    int p  = idx / NW_;
    int j  = idx - p * NW_;
    int k0 = 2 * p;
    float g0 = gamma[k0]     + 1.f;
    float g1 = gamma[k0 + 1] + 1.f;
    float w0, w1;
    if (j < 20) { w0 = afn[k0 * 20 + j];                w1 = afn[(k0 + 1) * 20 + j]; }
    else        { int jj = j - 20; w0 = bfn[k0 * 4 + jj]; w1 = bfn[(k0 + 1) * 4 + jj]; }
    g_wpack[idx] = make_float2(w0 * g0, w1 * g1);
}

// ---------------------------------------------------------------------------
// Kernel 1: per-token reductions (sumsq + 24 folded dots).
// 32 tokens per CTA (lane = token), 8 warps split the k-pairs of each chunk.
// X and W chunks triple-buffered in smem via cp.async (one barrier per chunk).
// Writes g_dots[tok*32 + 0..24].
// ---------------------------------------------------------------------------
__global__ void __launch_bounds__(256, 2)
reduce_kernel(const float* __restrict__ residuals)
{
    __shared__ __align__(16) char smem_raw[3 * TOK_ * XROW_ * 4 + 3 * PAIRS_ * NW_ * 8]; // 44544 B
    float*  xs  = (float*) smem_raw;                           // [3][TOK_][XROW_]
    float2* ws  = (float2*)(smem_raw + 3 * TOK_ * XROW_ * 4);  // [3][PAIRS_][NW_]
    float*  red = (float*) smem_raw;                           // alias (used after main loop)

    const int tid  = threadIdx.x;
    const int lane = tid & 31;
    const int warp = tid >> 5;
    const int tok0 = blockIdx.x * TOK_;
    const int b    = tok0 >> 11;             // token tile never crosses a batch boundary
    const int n0   = tok0 & (NSEQ_ - 1);
    const int t    = tid >> 3;               // token loaded by this thread (0..31)
    const int l8   = tid & 7;

    // chunk c covers global k in [c*64, (c+1)*64): stream s = c/32, d0 = (c%32)*64
#define STAGE(c_, buf_) do {                                                              \
        const int s_  = (c_) >> 5;                                                        \
        const int d0_ = ((c_) & 31) << 6;                                                 \
        const float* src_ = residuals +                                                   \
            ((((size_t)(b * S_ + s_)) * NSEQ_ + (size_t)(n0 + t)) * DIM_ + d0_);          \
        float* dx_ = xs + ((buf_) * TOK_ + t) * XROW_;                                    \
        __pipeline_memcpy_async(dx_ + l8 * 4,       src_ + l8 * 4,       16);             \
        __pipeline_memcpy_async(dx_ + (l8 + 8) * 4, src_ + (l8 + 8) * 4, 16);             \
        const float4* wsrc_ = (const float4*)(g_wpack + (size_t)(c_) * PAIRS_ * NW_);     \
        float4* wdst_ = (float4*)(ws + (buf_) * PAIRS_ * NW_);                            \
        for (int i_ = tid; i_ < PAIRS_ * NW_ / 2; i_ += 256)                              \
            __pipeline_memcpy_async(wdst_ + i_, wsrc_ + i_, 16);                          \
    } while (0)

    float2 acc[NACC_];
#pragma unroll
    for (int j = 0; j < NACC_; j++) acc[j] = make_float2(0.f, 0.f);

    STAGE(0, 0); __pipeline_commit();
    STAGE(1, 1); __pipeline_commit();

    for (int c = 0; c < NCHUNK_; c++) {
        __pipeline_wait_prior(1);        // chunk c fully staged
        __syncthreads();                 // copies visible to all; buffer (c+2)%3 free

        const int cb = c % 3;
        const float*  xrow  = xs + (cb * TOK_ + lane) * XROW_;
        const float2* wbase = ws + cb * PAIRS_ * NW_;
#pragma unroll
        for (int p = 0; p < 4; p++) {
            const int pr = warp * 4 + p;                      // pair row within chunk
            float2 x2 = *(const float2*)(xrow + 2 * pr);      // (even k, odd k)
            const float4* wv = (const float4*)(wbase + pr * NW_);  // lane-broadcast reads
#pragma unroll
            for (int j4 = 0; j4 < 12; j4++) {
                float4 w = wv[j4];
                acc[2 * j4]     = ffma2(x2, make_float2(w.x, w.y), acc[2 * j4]);
                acc[2 * j4 + 1] = ffma2(x2, make_float2(w.z, w.w), acc[2 * j4 + 1]);
            }
            acc[24] = ffma2(x2, x2, acc[24]);                 // sumsq
        }

        if (c + 2 < NCHUNK_) { STAGE(c + 2, (c + 2) % 3); }
        __pipeline_commit();             // commit (possibly empty) keeps group accounting aligned
    }
#undef STAGE

    // ---- cross-warp reduction (smem reuse is safe: all cp.async groups drained) ----
    __syncthreads();
#pragma unroll
    for (int j = 0; j < NACC_; j++)
        red[(warp * TOK_ + lane) * NACC_ + j] = acc[j].x + acc[j].y;
    __syncthreads();

    for (int idx = tid; idx < TOK_ * NACC_; idx += 256) {
        int tt = idx / NACC_;
        int j  = idx - tt * NACC_;
        float sm = 0.f;
#pragma unroll
        for (int w = 0; w < 8; w++) sm += red[(w * TOK_ + tt) * NACC_ + j];
        g_dots[(size_t)(tok0 + tt) * 32 + j] = sm;
    }
}

// ---------------------------------------------------------------------------
// Kernel 2: per-token epilogue -> 4x4 mixing matrix.
//   scale = sqrt(8192)/max(||x||,eps); P, M from alpha; 20 Sinkhorn iters
//   (column LSE over s, then row LSE over t); beta;
//   C[so][s] = beta[so]*P[s] + exp(M[s][so]).
// ---------------------------------------------------------------------------
__global__ void coef_kernel(const float* __restrict__ sa,   // static_alpha (4,5)
                            const float* __restrict__ pbs,  // pre_branch_scale (1,)
                            const float* __restrict__ rsc,  // residual_scale (1,)
                            const float* __restrict__ sb,   // static_beta (4,)
                            const float* __restrict__ hps)  // h_post_scale scalar
{
    int tok = blockIdx.x * blockDim.x + threadIdx.x;
    if (tok >= NTOK_) return;

    float vv[NACC_];
    const float* v = g_dots + (size_t)tok * 32;
#pragma unroll
    for (int j = 0; j < NACC_; j++) vv[j] = v[j];

    const float scale = 90.50966799187809f / fmaxf(sqrtf(vv[24]), 1e-12f); // sqrt(S*d*FR)/max(nrm,eps)
    const float pre = pbs[0] * scale;
    const float rs  = rsc[0] * scale;
    const float hp  = hps[0] * scale;

    float P[4], M[4][4];
#pragma unroll
    for (int s = 0; s < 4; s++) {
        P[s] = 1.f / (1.f + __expf(-(vv[s * 5] * pre + sa[s * 5])));
#pragma unroll
        for (int tt = 0; tt < 4; tt++)
            M[s][tt] = vv[s * 5 + 1 + tt] * rs + sa[s * 5 + 1 + tt];
    }

    for (int it = 0; it < 20; it++) {
        // column LSE (over s)
#pragma unroll
        for (int tt = 0; tt < 4; tt++) {
            float m = fmaxf(fmaxf(M[0][tt], M[1][tt]), fmaxf(M[2][tt], M[3][tt]));
            float sm = __expf(M[0][tt] - m) + __expf(M[1][tt] - m)
                     + __expf(M[2][tt] - m) + __expf(M[3][tt] - m);
            float l = m + __logf(sm);
            M[0][tt] -= l; M[1][tt] -= l; M[2][tt] -= l; M[3][tt] -= l;
        }
        // row LSE (over t)
#pragma unroll
        for (int s = 0; s < 4; s++) {
            float m = fmaxf(fmaxf(M[s][0], M[s][1]), fmaxf(M[s][2], M[s][3]));
            float sm = __expf(M[s][0] - m) + __expf(M[s][1] - m)
                     + __expf(M[s][2] - m) + __expf(M[s][3] - m);
            float l = m + __logf(sm);
            M[s][0] -= l; M[s][1] -= l; M[s][2] -= l; M[s][3] -= l;
        }
    }

    float beta[4];
#pragma unroll
    for (int so = 0; so < 4; so++)
        beta[so] = 2.f / (1.f + __expf(-(vv[20 + so] * hp + sb[so])));

#pragma unroll
    for (int so = 0; so < 4; so++)
#pragma unroll
        for (int s = 0; s < 4; s++)
            g_coef[(size_t)tok * 16 + so * 4 + s] = beta[so] * P[s] + __expf(M[s][so]);
}

// ---------------------------------------------------------------------------
// Kernel 3: streaming mix.  out[b*4+so, n, d] = sum_s C[so][s] * r[b*4+s, n, d]
// One CTA per (b, n); 512 threads, one float4 each. Pure memory streaming.
// ---------------------------------------------------------------------------
__global__ void __launch_bounds__(512)
mix_kernel(const float* __restrict__ residuals, float* __restrict__ out)
{
    __shared__ float C[16];
    const int blk = blockIdx.x;            // b*2048 + n == token id
    const int b   = blk >> 11;
    const int n   = blk & (NSEQ_ - 1);
    if (threadIdx.x < 16) C[threadIdx.x] = g_coef[(size_t)blk * 16 + threadIdx.x];
    __syncthreads();

    const size_t str  = (size_t)NSEQ_ * (DIM_ / 4);                      // float4 per stream
    const size_t base = ((size_t)(b * S_) * NSEQ_ + n) * (DIM_ / 4) + threadIdx.x;
    const float4* in = (const float4*)residuals;
    float4*       ov = (float4*)out;

    float4 r0 = in[base];
    float4 r1 = in[base + str];
    float4 r2 = in[base + 2 * str];
    float4 r3 = in[base + 3 * str];

#pragma unroll
    for (int so = 0; so < 4; so++) {
        float c0 = C[so * 4 + 0], c1 = C[so * 4 + 1], c2 = C[so * 4 + 2], c3 = C[so * 4 + 3];
        float4 o;
        o.x = c0 * r0.x + c1 * r1.x + c2 * r2.x + c3 * r3.x;
        o.y = c0 * r0.y + c1 * r1.y + c2 * r2.y + c3 * r3.y;
        o.z = c0 * r0.z + c1 * r1.z + c2 * r2.z + c3 * r3.z;
        o.w = c0 * r0.w + c1 * r1.w + c2 * r2.w + c3 * r3.w;
        ov[base + (size_t)so * str] = o;
    }
}

// ---------------------------------------------------------------------------
extern "C" void kernel_launch(void* const* d_in, const int* in_sizes, int n_in,
                              void* d_out, int out_size)
{
    const float* residuals = (const float*)d_in[0];
    const float* gamma     = (const float*)d_in[1];
    const float* afn       = (const float*)d_in[2];
    const float* sa        = (const float*)d_in[3];
    const float* pbs       = (const float*)d_in[4];
    const float* rsc       = (const float*)d_in[5];
    const float* bfn       = (const float*)d_in[6];
    const float* sb        = (const float*)d_in[7];
    const float* hps       = (const float*)d_in[8];
    float* out = (float*)d_out;

    prep_kernel<<<((KTOT_ / 2) * NW_ + 255) / 256, 256>>>(gamma, afn, bfn);
    reduce_kernel<<<NTOK_ / TOK_, 256>>>(residuals);
    coef_kernel<<<NTOK_ / 256, 256>>>(sa, pbs, rsc, sb, hps);
    mix_kernel<<<B_ * NSEQ_, 512>>>(residuals, out);
}

// round 9
// speedup vs baseline: 1.0385x; 1.0385x over previous
#include <cuda_runtime.h>
#include <cuda_pipeline.h>
#include <cstdint>
#include <cstddef>

// ---------------- problem constants (fixed by dataset) ----------------
#define S_      4
#define DIM_    2048
#define NSEQ_   2048
#define B_      4
#define KTOT_   8192          // S*DIM
#define NTOK_   8192          // B*N
#define NW_     24            // 20 alpha cols + 4 beta cols
#define NACC_   25            // 24 dots + sumsq
#define TOK_    32            // tokens per reduce CTA
#define KC_     64            // k elements per chunk
#define PAIRS_  32            // k-pairs per chunk
#define NCHUNK_ 128           // KTOT_/KC_
#define XROW_   68            // padded smem row (floats); 272B rows keep 16B cp.async alignment

#define XS_BYTES_ (3 * TOK_ * XROW_ * 4)        // 26112
#define WS_BYTES_ (3 * PAIRS_ * NW_ * 8)        // 18432

// ---------------- device scratch (no allocation allowed) ----------------
__device__ __align__(16) float2 g_wpack[(KTOT_ / 2) * NW_];  // 768 KB packed folded weights
__device__ __align__(16) float  g_coef[NTOK_ * 16];          // per-token 4x4 mixing matrix

// Packed fp32x2 FMA (Blackwell FFMA2): 2 MACs per issue slot.
__device__ __forceinline__ float2 ffma2(float2 a, float2 b, float2 c) {
    float2 d;
    asm("fma.rn.f32x2 %0, %1, %2, %3;"
        : "=l"(*reinterpret_cast<unsigned long long*>(&d))
        : "l"(*reinterpret_cast<const unsigned long long*>(&a)),
          "l"(*reinterpret_cast<const unsigned long long*>(&b)),
          "l"(*reinterpret_cast<const unsigned long long*>(&c)));
    return d;
}

// 16B shared load that lands as TWO aligned 64-bit register pairs (FFMA2-ready).
__device__ __forceinline__ void lds_2xf2(uint32_t addr, float2& a, float2& b) {
    asm volatile("ld.shared.v2.b64 {%0, %1}, [%2];"
        : "=l"(*reinterpret_cast<unsigned long long*>(&a)),
          "=l"(*reinterpret_cast<unsigned long long*>(&b))
        : "r"(addr));
}

// ---------------------------------------------------------------------------
// Kernel 0: fold gamma into the weights and interleave by k-parity:
//   g_wpack[p*24 + j] = ( (1+g[2p])*W[2p][j], (1+g[2p+1])*W[2p+1][j] )
// ---------------------------------------------------------------------------
__global__ void prep_kernel(const float* __restrict__ gamma,
                            const float* __restrict__ afn,   // (8192, 20)
                            const float* __restrict__ bfn)   // (8192, 4)
{
    int idx = blockIdx.x * blockDim.x + threadIdx.x;
    if (idx >= (KTOT_ / 2) * NW_) return;
    int p  = idx / NW_;
    int j  = idx - p * NW_;
    int k0 = 2 * p;
    float g0 = gamma[k0]     + 1.f;
    float g1 = gamma[k0 + 1] + 1.f;
    float w0, w1;
    if (j < 20) { w0 = afn[k0 * 20 + j];                w1 = afn[(k0 + 1) * 20 + j]; }
    else        { int jj = j - 20; w0 = bfn[k0 * 4 + jj]; w1 = bfn[(k0 + 1) * 4 + jj]; }
    g_wpack[idx] = make_float2(w0 * g0, w1 * g1);
}

// ---------------------------------------------------------------------------
// Kernel 1: per-token reductions (sumsq + 24 folded dots) + fused Sinkhorn
// epilogue producing the per-token 4x4 mixing matrix.
// 32 tokens per CTA (lane = token), 8 warps split the k-pairs of each chunk.
// All smem operand loads go through ld.shared.v2.b64 so every FFMA2 operand
// is a guaranteed-aligned register pair (no repacking MOVs).
// ---------------------------------------------------------------------------
__global__ void __launch_bounds__(256, 2)
reduce_kernel(const float* __restrict__ residuals,
              const float* __restrict__ sa,   // static_alpha (4,5)
              const float* __restrict__ pbs,  // pre_branch_scale (1,)
              const float* __restrict__ rsc,  // residual_scale (1,)
              const float* __restrict__ sb,   // static_beta (4,)
              const float* __restrict__ hps)  // h_post_scale scalar
{
    __shared__ __align__(16) char smem_raw[XS_BYTES_ + WS_BYTES_]; // 44544 B
    float*  xs  = (float*) smem_raw;                      // [3][TOK_][XROW_]
    float2* ws  = (float2*)(smem_raw + XS_BYTES_);        // [3][PAIRS_][NW_]
    float*  red = (float*) smem_raw;                      // alias (post-loop)

    const uint32_t xs_base = (uint32_t)__cvta_generic_to_shared(smem_raw);
    const uint32_t ws_base = xs_base + XS_BYTES_;

    const int tid  = threadIdx.x;
    const int lane = tid & 31;
    const int warp = tid >> 5;
    const int tok0 = blockIdx.x * TOK_;
    const int b    = tok0 >> 11;             // token tile never crosses a batch boundary
    const int n0   = tok0 & (NSEQ_ - 1);
    const int t    = tid >> 3;               // token loaded by this thread (0..31)
    const int l8   = tid & 7;

    // chunk c covers global k in [c*64, (c+1)*64): stream s = c/32, d0 = (c%32)*64
#define STAGE(c_, buf_) do {                                                              \
        const int s_  = (c_) >> 5;                                                        \
        const int d0_ = ((c_) & 31) << 6;                                                 \
        const float* src_ = residuals +                                                   \
            ((((size_t)(b * S_ + s_)) * NSEQ_ + (size_t)(n0 + t)) * DIM_ + d0_);          \
        float* dx_ = xs + ((buf_) * TOK_ + t) * XROW_;                                    \
        __pipeline_memcpy_async(dx_ + l8 * 4,       src_ + l8 * 4,       16);             \
        __pipeline_memcpy_async(dx_ + (l8 + 8) * 4, src_ + (l8 + 8) * 4, 16);             \
        const float4* wsrc_ = (const float4*)(g_wpack + (size_t)(c_) * PAIRS_ * NW_);     \
        float4* wdst_ = (float4*)(ws + (buf_) * PAIRS_ * NW_);                            \
        for (int i_ = tid; i_ < PAIRS_ * NW_ / 2; i_ += 256)                              \
            __pipeline_memcpy_async(wdst_ + i_, wsrc_ + i_, 16);                          \
    } while (0)

    float2 acc[NACC_];
#pragma unroll
    for (int j = 0; j < NACC_; j++) acc[j] = make_float2(0.f, 0.f);

    STAGE(0, 0); __pipeline_commit();
    STAGE(1, 1); __pipeline_commit();

    for (int c = 0; c < NCHUNK_; c++) {
        __pipeline_wait_prior(1);        // chunk c fully staged
        __syncthreads();                 // copies visible; buffer (c+2)%3 free

        const int cb = c % 3;
        const uint32_t xaddr = xs_base + (uint32_t)((cb * TOK_ + lane) * XROW_) * 4u;
        const uint32_t waddr = ws_base + (uint32_t)(cb * PAIRS_ * NW_) * 8u;

#pragma unroll
        for (int e = 0; e < 2; e++) {
            const int pr0 = warp * 4 + 2 * e;           // even pair row
            float2 xa, xb;                              // x pairs pr0, pr0+1
            lds_2xf2(xaddr + 8u * pr0, xa, xb);

            const uint32_t wa = waddr + (uint32_t)pr0 * 192u;
#pragma unroll
            for (int m = 0; m < 12; m++) {
                float2 w0, w1;
                lds_2xf2(wa + m * 16u, w0, w1);
                acc[2 * m]     = ffma2(xa, w0, acc[2 * m]);
                acc[2 * m + 1] = ffma2(xa, w1, acc[2 * m + 1]);
            }
            acc[24] = ffma2(xa, xa, acc[24]);

            const uint32_t wb = wa + 192u;
#pragma unroll
            for (int m = 0; m < 12; m++) {
                float2 w0, w1;
                lds_2xf2(wb + m * 16u, w0, w1);
                acc[2 * m]     = ffma2(xb, w0, acc[2 * m]);
                acc[2 * m + 1] = ffma2(xb, w1, acc[2 * m + 1]);
            }
            acc[24] = ffma2(xb, xb, acc[24]);
        }

        if (c + 2 < NCHUNK_) { STAGE(c + 2, (c + 2) % 3); }
        __pipeline_commit();             // keeps group accounting aligned
    }
#undef STAGE

    // ---- cross-warp reduction (all cp.async drained; smem reuse safe) ----
    __syncthreads();
#pragma unroll
    for (int j = 0; j < NACC_; j++)
        red[(warp * TOK_ + lane) * NACC_ + j] = acc[j].x + acc[j].y;
    __syncthreads();

    // ---- fused per-token epilogue: thread tt<32 handles token tok0+tt ----
    if (tid < TOK_) {
        const int tt = tid;
        float vv[NACC_];
#pragma unroll
        for (int j = 0; j < NACC_; j++) {
            float sm = 0.f;
#pragma unroll
            for (int w = 0; w < 8; w++) sm += red[(w * TOK_ + tt) * NACC_ + j];
            vv[j] = sm;
        }

        const float scale = 90.50966799187809f / fmaxf(sqrtf(vv[24]), 1e-12f);
        const float pre = pbs[0] * scale;
        const float rs  = rsc[0] * scale;
        const float hp  = hps[0] * scale;

        float P[4], M[4][4];
#pragma unroll
        for (int s = 0; s < 4; s++) {
            P[s] = 1.f / (1.f + __expf(-(vv[s * 5] * pre + sa[s * 5])));
#pragma unroll
            for (int u = 0; u < 4; u++)
                M[s][u] = vv[s * 5 + 1 + u] * rs + sa[s * 5 + 1 + u];
        }

        for (int it = 0; it < 20; it++) {
            // column LSE (over s)
#pragma unroll
            for (int u = 0; u < 4; u++) {
                float m = fmaxf(fmaxf(M[0][u], M[1][u]), fmaxf(M[2][u], M[3][u]));
                float sm = __expf(M[0][u] - m) + __expf(M[1][u] - m)
                         + __expf(M[2][u] - m) + __expf(M[3][u] - m);
                float l = m + __logf(sm);
                M[0][u] -= l; M[1][u] -= l; M[2][u] -= l; M[3][u] -= l;
            }
            // row LSE (over t)
#pragma unroll
            for (int s = 0; s < 4; s++) {
                float m = fmaxf(fmaxf(M[s][0], M[s][1]), fmaxf(M[s][2], M[s][3]));
                float sm = __expf(M[s][0] - m) + __expf(M[s][1] - m)
                         + __expf(M[s][2] - m) + __expf(M[s][3] - m);
                float l = m + __logf(sm);
                M[s][0] -= l; M[s][1] -= l; M[s][2] -= l; M[s][3] -= l;
            }
        }

        float beta[4];
#pragma unroll
        for (int so = 0; so < 4; so++)
            beta[so] = 2.f / (1.f + __expf(-(vv[20 + so] * hp + sb[so])));

#pragma unroll
        for (int so = 0; so < 4; so++)
#pragma unroll
            for (int s = 0; s < 4; s++)
                g_coef[(size_t)(tok0 + tt) * 16 + so * 4 + s] =
                    beta[so] * P[s] + __expf(M[s][so]);
    }
}

// ---------------------------------------------------------------------------
// Kernel 2: streaming mix.  out[b*4+so, n, d] = sum_s C[so][s] * r[b*4+s, n, d]
// One CTA per (b, n); 512 threads, one float4 each. Already at DRAM roofline.
// ---------------------------------------------------------------------------
__global__ void __launch_bounds__(512)
mix_kernel(const float* __restrict__ residuals, float* __restrict__ out)
{
    __shared__ float C[16];
    const int blk = blockIdx.x;            // b*2048 + n == token id
    const int b   = blk >> 11;
    const int n   = blk & (NSEQ_ - 1);
    if (threadIdx.x < 16) C[threadIdx.x] = g_coef[(size_t)blk * 16 + threadIdx.x];
    __syncthreads();

    const size_t str  = (size_t)NSEQ_ * (DIM_ / 4);                      // float4 per stream
    const size_t base = ((size_t)(b * S_) * NSEQ_ + n) * (DIM_ / 4) + threadIdx.x;
    const float4* in = (const float4*)residuals;
    float4*       ov = (float4*)out;

    float4 r0 = in[base];
    float4 r1 = in[base + str];
    float4 r2 = in[base + 2 * str];
    float4 r3 = in[base + 3 * str];

#pragma unroll
    for (int so = 0; so < 4; so++) {
        float c0 = C[so * 4 + 0], c1 = C[so * 4 + 1], c2 = C[so * 4 + 2], c3 = C[so * 4 + 3];
        float4 o;
        o.x = c0 * r0.x + c1 * r1.x + c2 * r2.x + c3 * r3.x;
        o.y = c0 * r0.y + c1 * r1.y + c2 * r2.y + c3 * r3.y;
        o.z = c0 * r0.z + c1 * r1.z + c2 * r2.z + c3 * r3.z;
        o.w = c0 * r0.w + c1 * r1.w + c2 * r2.w + c3 * r3.w;
        ov[base + (size_t)so * str] = o;
    }
}

// ---------------------------------------------------------------------------
extern "C" void kernel_launch(void* const* d_in, const int* in_sizes, int n_in,
                              void* d_out, int out_size)
{
    const float* residuals = (const float*)d_in[0];
    const float* gamma     = (const float*)d_in[1];
    const float* afn       = (const float*)d_in[2];
    const float* sa        = (const float*)d_in[3];
    const float* pbs       = (const float*)d_in[4];
    const float* rsc       = (const float*)d_in[5];
    const float* bfn       = (const float*)d_in[6];
    const float* sb        = (const float*)d_in[7];
    const float* hps       = (const float*)d_in[8];
    float* out = (float*)d_out;

    prep_kernel<<<((KTOT_ / 2) * NW_ + 255) / 256, 256>>>(gamma, afn, bfn);
    reduce_kernel<<<NTOK_ / TOK_, 256>>>(residuals, sa, pbs, rsc, sb, hps);
    mix_kernel<<<B_ * NSEQ_, 512>>>(residuals, out);
}

// round 10
// speedup vs baseline: 1.2535x; 1.2070x over previous
#include <cuda_runtime.h>
#include <cuda_pipeline.h>
#include <cstdint>
#include <cstddef>

// ---------------- problem constants (fixed by dataset) ----------------
#define S_      4
#define DIM_    2048
#define NSEQ_   2048
#define B_      4
#define KTOT_   8192          // S*DIM
#define NTOK_   8192          // B*N
#define NW_     24            // 20 alpha cols + 4 beta cols
#define NACC_   25            // 24 dots + sumsq
#define TOKM_   32            // tokens per reduce CTA (2 warps x 16)
#define KC2_    64            // k elements per chunk
#define NCHUNK_ 128           // KTOT_/KC2_
#define XROW_   68            // padded smem row (words); 68 % 32 == 4 -> conflict-free A loads

// ---------------- device scratch (no allocation allowed) ----------------
__device__ __align__(16) uint32_t g_wt[KTOT_ * NW_];   // 768 KB folded W', tf32-rounded fp32 bits
__device__ __align__(16) float    g_coef[NTOK_ * 16];  // per-token 4x4 mixing matrix

// m16n8k8 tf32 MMA: D(16x8,f32) += A(16x8,tf32) * B(8x8,tf32)
__device__ __forceinline__ void mma_tf32(float d[4],
                                         uint32_t a0, uint32_t a1, uint32_t a2, uint32_t a3,
                                         uint32_t b0, uint32_t b1)
{
    asm volatile(
        "mma.sync.aligned.m16n8k8.row.col.f32.tf32.tf32.f32 "
        "{%0,%1,%2,%3}, {%4,%5,%6,%7}, {%8,%9}, {%0,%1,%2,%3};"
        : "+f"(d[0]), "+f"(d[1]), "+f"(d[2]), "+f"(d[3])
        : "r"(a0), "r"(a1), "r"(a2), "r"(a3), "r"(b0), "r"(b1));
}

// ---------------------------------------------------------------------------
// Kernel 0: fold gamma into the weights, round to tf32, store row-major [k][24]:
//   g_wt[k*24 + j] = tf32( (1+gamma[k]) * [A|B][k][j] )
// ---------------------------------------------------------------------------
__global__ void prep_kernel(const float* __restrict__ gamma,
                            const float* __restrict__ afn,   // (8192, 20)
                            const float* __restrict__ bfn)   // (8192, 4)
{
    int idx = blockIdx.x * blockDim.x + threadIdx.x;
    if (idx >= KTOT_ * NW_) return;
    int k = idx / NW_;
    int j = idx - k * NW_;
    float g = gamma[k] + 1.f;
    float w = (j < 20) ? afn[k * 20 + j] : bfn[k * 4 + (j - 20)];
    uint32_t t;
    asm("cvt.rna.tf32.f32 %0, %1;" : "=r"(t) : "f"(w * g));
    g_wt[idx] = t;
}

// ---------------------------------------------------------------------------
// Kernel 1: tensor-core GEMV (24 dots via mma.sync tf32) + fp32 sumsq + fused
// Sinkhorn epilogue. 32 tokens per CTA; warp w owns tokens w*16..w*16+15 and
// iterates the full K. Triple-buffered cp.async staging of x and W chunks.
//
// Fragment layout (PTX m16n8k8):
//   A: a0=(gid,tig) a1=(gid+8,tig) a2=(gid,tig+4) a3=(gid+8,tig+4)
//   B: b0=(k=tig,n=gid) b1=(k=tig+4,n=gid)
//   D: d0=(gid,2tig) d1=(gid,2tig+1) d2=(gid+8,2tig) d3=(gid+8,2tig+1)
// ---------------------------------------------------------------------------
__global__ void __launch_bounds__(64)
reduce_kernel(const float* __restrict__ residuals,
              const float* __restrict__ sa,   // static_alpha (4,5)
              const float* __restrict__ pbs,  // pre_branch_scale (1,)
              const float* __restrict__ rsc,  // residual_scale (1,)
              const float* __restrict__ sb,   // static_beta (4,)
              const float* __restrict__ hps)  // h_post_scale scalar
{
    __shared__ __align__(16) uint32_t xs[3][TOKM_][XROW_];  // 26112 B (fp32 bits)
    __shared__ __align__(16) uint32_t wsm[3][KC2_][NW_];    // 18432 B (tf32 bits)
    __shared__ float red[TOKM_][26];                        //  3328 B

    const int tid  = threadIdx.x;
    const int lane = tid & 31;
    const int warp = tid >> 5;           // 0 or 1
    const int gid  = lane >> 2;          // 0..7
    const int tig  = lane & 3;           // 0..3
    const int tok0 = blockIdx.x * TOKM_;
    const int b    = tok0 >> 11;         // tile never crosses a batch boundary
    const int n0   = tok0 & (NSEQ_ - 1);

    // chunk c covers global k in [c*64,(c+1)*64): stream s = c/32, d0 = (c%32)*64
#define STAGE(c_, buf_) do {                                                               \
        const int s_  = (c_) >> 5;                                                         \
        const int d0_ = ((c_) & 31) << 6;                                                  \
        { int tok_ = tid >> 1; int q0_ = (tid & 1) * 8;                                    \
          const float* src_ = residuals +                                                  \
              ((((size_t)(b * S_ + s_)) * NSEQ_ + (size_t)(n0 + tok_)) * DIM_ + d0_ + q0_ * 4); \
          float* dx_ = (float*)&xs[buf_][tok_][q0_ * 4];                                   \
          _Pragma("unroll")                                                                \
          for (int q_ = 0; q_ < 8; q_++)                                                   \
              __pipeline_memcpy_async(dx_ + q_ * 4, src_ + q_ * 4, 16);                    \
        }                                                                                  \
        { const uint32_t* wsrc_ = g_wt + (size_t)(c_) * KC2_ * NW_;                        \
          uint32_t* wdst_ = &wsm[buf_][0][0];                                              \
          _Pragma("unroll")                                                                \
          for (int i_ = tid; i_ < KC2_ * NW_ / 4; i_ += 64)                                \
              __pipeline_memcpy_async(wdst_ + i_ * 4, wsrc_ + i_ * 4, 16);                 \
        }                                                                                  \
    } while (0)

    float d[3][4];
#pragma unroll
    for (int ng = 0; ng < 3; ng++)
#pragma unroll
        for (int r = 0; r < 4; r++) d[ng][r] = 0.f;
    float s0 = 0.f, s1 = 0.f;            // fp32 sumsq for rows gid, gid+8

    const int rowA = warp * 16 + gid;    // this lane's low token row

    STAGE(0, 0); __pipeline_commit();
    STAGE(1, 1); __pipeline_commit();

    for (int c = 0; c < NCHUNK_; c++) {
        __pipeline_wait_prior(1);        // chunk c fully staged
        __syncthreads();                 // visible to all; buffer (c+2)%3 free

        const int buf = c % 3;
#pragma unroll
        for (int kk = 0; kk < 8; kk++) {
            const int k0 = kk * 8;
            uint32_t a0 = xs[buf][rowA][k0 + tig];
            uint32_t a1 = xs[buf][rowA + 8][k0 + tig];
            uint32_t a2 = xs[buf][rowA][k0 + tig + 4];
            uint32_t a3 = xs[buf][rowA + 8][k0 + tig + 4];

            // exact fp32 sumsq from the untruncated x bits
            float f0 = __uint_as_float(a0), f1 = __uint_as_float(a1);
            float f2 = __uint_as_float(a2), f3 = __uint_as_float(a3);
            s0 = fmaf(f0, f0, s0); s0 = fmaf(f2, f2, s0);
            s1 = fmaf(f1, f1, s1); s1 = fmaf(f3, f3, s1);

#pragma unroll
            for (int ng = 0; ng < 3; ng++) {
                uint32_t b0 = wsm[buf][k0 + tig][ng * 8 + gid];
                uint32_t b1 = wsm[buf][k0 + tig + 4][ng * 8 + gid];
                mma_tf32(d[ng], a0, a1, a2, a3, b0, b1);
            }
        }

        if (c + 2 < NCHUNK_) { STAGE(c + 2, (c + 2) % 3); }
        __pipeline_commit();             // keeps group accounting aligned
    }
#undef STAGE

    // ---- gather dots into red[token][0..24] ----
    const int tokA = warp * 16 + gid;
    const int tokB = tokA + 8;
#pragma unroll
    for (int ng = 0; ng < 3; ng++) {
        red[tokA][ng * 8 + tig * 2]     = d[ng][0];
        red[tokA][ng * 8 + tig * 2 + 1] = d[ng][1];
        red[tokB][ng * 8 + tig * 2]     = d[ng][2];
        red[tokB][ng * 8 + tig * 2 + 1] = d[ng][3];
    }
    // sumsq: reduce across the 4 lanes of each group
    s0 += __shfl_xor_sync(0xffffffffu, s0, 1);
    s0 += __shfl_xor_sync(0xffffffffu, s0, 2);
    s1 += __shfl_xor_sync(0xffffffffu, s1, 1);
    s1 += __shfl_xor_sync(0xffffffffu, s1, 2);
    if (tig == 0) { red[tokA][24] = s0; red[tokB][24] = s1; }
    __syncthreads();

    // ---- fused per-token epilogue: warp 0, lane tt handles token tok0+tt ----
    if (tid < TOKM_) {
        const int tt = tid;
        float vv[NACC_];
#pragma unroll
        for (int j = 0; j < NACC_; j++) vv[j] = red[tt][j];

        const float scale = 90.50966799187809f / fmaxf(sqrtf(vv[24]), 1e-12f);
        const float pre = pbs[0] * scale;
        const float rs  = rsc[0] * scale;
        const float hp  = hps[0] * scale;

        float P[4], M[4][4];
#pragma unroll
        for (int s = 0; s < 4; s++) {
            P[s] = 1.f / (1.f + __expf(-(vv[s * 5] * pre + sa[s * 5])));
#pragma unroll
            for (int u = 0; u < 4; u++)
                M[s][u] = vv[s * 5 + 1 + u] * rs + sa[s * 5 + 1 + u];
        }

        for (int it = 0; it < 20; it++) {
            // column LSE (over s)
#pragma unroll
            for (int u = 0; u < 4; u++) {
                float m = fmaxf(fmaxf(M[0][u], M[1][u]), fmaxf(M[2][u], M[3][u]));
                float sm = __expf(M[0][u] - m) + __expf(M[1][u] - m)
                         + __expf(M[2][u] - m) + __expf(M[3][u] - m);
                float l = m + __logf(sm);
                M[0][u] -= l; M[1][u] -= l; M[2][u] -= l; M[3][u] -= l;
            }
            // row LSE (over t)
#pragma unroll
            for (int s = 0; s < 4; s++) {
                float m = fmaxf(fmaxf(M[s][0], M[s][1]), fmaxf(M[s][2], M[s][3]));
                float sm = __expf(M[s][0] - m) + __expf(M[s][1] - m)
                         + __expf(M[s][2] - m) + __expf(M[s][3] - m);
                float l = m + __logf(sm);
                M[s][0] -= l; M[s][1] -= l; M[s][2] -= l; M[s][3] -= l;
            }
        }

        float beta[4];
#pragma unroll
        for (int so = 0; so < 4; so++)
            beta[so] = 2.f / (1.f + __expf(-(vv[20 + so] * hp + sb[so])));

#pragma unroll
        for (int so = 0; so < 4; so++)
#pragma unroll
            for (int s = 0; s < 4; s++)
                g_coef[(size_t)(tok0 + tt) * 16 + so * 4 + s] =
                    beta[so] * P[s] + __expf(M[s][so]);
    }
}

// ---------------------------------------------------------------------------
// Kernel 2: streaming mix.  out[b*4+so, n, d] = sum_s C[so][s] * r[b*4+s, n, d]
// One CTA per (b, n); 512 threads, one float4 each. Already at DRAM roofline.
// ---------------------------------------------------------------------------
__global__ void __launch_bounds__(512)
mix_kernel(const float* __restrict__ residuals, float* __restrict__ out)
{
    __shared__ float C[16];
    const int blk = blockIdx.x;            // b*2048 + n == token id
    const int b   = blk >> 11;
    const int n   = blk & (NSEQ_ - 1);
    if (threadIdx.x < 16) C[threadIdx.x] = g_coef[(size_t)blk * 16 + threadIdx.x];
    __syncthreads();

    const size_t str  = (size_t)NSEQ_ * (DIM_ / 4);                      // float4 per stream
    const size_t base = ((size_t)(b * S_) * NSEQ_ + n) * (DIM_ / 4) + threadIdx.x;
    const float4* in = (const float4*)residuals;
    float4*       ov = (float4*)out;

    float4 r0 = in[base];
    float4 r1 = in[base + str];
    float4 r2 = in[base + 2 * str];
    float4 r3 = in[base + 3 * str];

#pragma unroll
    for (int so = 0; so < 4; so++) {
        float c0 = C[so * 4 + 0], c1 = C[so * 4 + 1], c2 = C[so * 4 + 2], c3 = C[so * 4 + 3];
        float4 o;
        o.x = c0 * r0.x + c1 * r1.x + c2 * r2.x + c3 * r3.x;
        o.y = c0 * r0.y + c1 * r1.y + c2 * r2.y + c3 * r3.y;
        o.z = c0 * r0.z + c1 * r1.z + c2 * r2.z + c3 * r3.z;
        o.w = c0 * r0.w + c1 * r1.w + c2 * r2.w + c3 * r3.w;
        ov[base + (size_t)so * str] = o;
    }
}

// ---------------------------------------------------------------------------
extern "C" void kernel_launch(void* const* d_in, const int* in_sizes, int n_in,
                              void* d_out, int out_size)
{
    const float* residuals = (const float*)d_in[0];
    const float* gamma     = (const float*)d_in[1];
    const float* afn       = (const float*)d_in[2];
    const float* sa        = (const float*)d_in[3];
    const float* pbs       = (const float*)d_in[4];
    const float* rsc       = (const float*)d_in[5];
    const float* bfn       = (const float*)d_in[6];
    const float* sb        = (const float*)d_in[7];
    const float* hps       = (const float*)d_in[8];
    float* out = (float*)d_out;

    prep_kernel<<<(KTOT_ * NW_ + 255) / 256, 256>>>(gamma, afn, bfn);
    reduce_kernel<<<NTOK_ / TOKM_, 64>>>(residuals, sa, pbs, rsc, sb, hps);
    mix_kernel<<<B_ * NSEQ_, 512>>>(residuals, out);
}